// round 13
// baseline (speedup 1.0000x reference)
#include <cuda_runtime.h>
#include <cstdint>
#include <math.h>
#include <float.h>

// ---------------------------------------------------------------------------
// MultiBoxLoss (SSD) fused loss.  B=32, P=8732, C=81.
//   out[0] = loss_c / N, out[1] = loss_l / N
// Per-warp cp.async pipeline: each warp owns a private double-buffered f32
// smem ring and streams 4 consecutive 32-prior slices through it with
// cp.async.wait_group + __syncwarp() ONLY -- no block barriers in the hot
// path, and slice i+1 loads overlap slice i compute inside every warp.
// nll = lse - tgt_logit is both the CE term and the hard-negative rank key.
// Common case (num_neg >= #negatives): loss_c = sum of ALL nll.
// Rare case: exact top-k via radix select (tie-order invariant for a sum).
// ---------------------------------------------------------------------------

#define BATCH    32
#define PRIORS   8732
#define CLASSES  81
#define TPB      96                                // 3 warps per block
#define NWARP    3
#define WROWS    32                                // priors per slice
#define SLICE_F  (WROWS * CLASSES)                 // 2592 floats per slice
#define SL_PER_B 273                               // slices per batch (272*32+28)
#define SL_TOTAL (SL_PER_B * BATCH)                // 8736
#define K_SL     4                                 // slices per warp
#define GRID_MAIN (SL_TOTAL / (NWARP * K_SL))      // 728
#define SMEM_BYTES (NWARP * 2 * SLICE_F * 4)       // 62,208 B
#define FULLMASK 0xFFFFFFFFu

// Device-global scratch; statically zero-init. The fused finalizer resets
// everything at the end of each call -> graph replays are deterministic.
__device__ double   g_sum_all[BATCH];
__device__ double   g_sum_pos[BATCH];
__device__ double   g_sum_loc[BATCH];
__device__ int      g_num_pos[BATCH];
__device__ unsigned g_done   = 0;
__device__ float    g_vrank[BATCH * PRIORS];

__device__ __forceinline__ void cp16(uint32_t dst, const void* src) {
    asm volatile("cp.async.cg.shared.global [%0], [%1], 16;"
                 :: "r"(dst), "l"(src));
}
__device__ __forceinline__ void cp_commit() {
    asm volatile("cp.async.commit_group;");
}
__device__ __forceinline__ void cp_wait1() {
    asm volatile("cp.async.wait_group 1;");
}

// Issue this lane's share of async copies for slice s into stage_smem.
__device__ __forceinline__ void issue_slice(
    const float* __restrict__ conf, uint32_t stage_smem, int s, int lane) {
    const int b  = s / SL_PER_B;
    const int j  = s % SL_PER_B;
    const int p0 = j * WROWS;
    const int nr = min(WROWS, PRIORS - p0);
    const long long gw = (long long)b * PRIORS + p0;   // gw*81 % 4 == 0
    const float4* src4 = (const float4*)(conf + gw * CLASSES);
    const int n4 = (nr * CLASSES) >> 2;                // 648 or 567
    for (int j4 = lane; j4 < n4; j4 += 32)
        cp16(stage_smem + j4 * 16, src4 + j4);
}

__global__ void __launch_bounds__(TPB)
k_main(const float* __restrict__ conf,
       const float4* __restrict__ loc,
       const void*  __restrict__ ct,
       const float4* __restrict__ loct,
       float* __restrict__ out, int out_size) {
    extern __shared__ __align__(16) float s_dyn[];   // [NWARP][2][SLICE_F]
    __shared__ unsigned s_last;
    __shared__ unsigned sh_prefix, sh_rare;
    __shared__ int      sh_k;
    __shared__ double   sh_lc, sh_ll;
    __shared__ long long sh_n;

    // finalizer scratch aliases the ring (used only by the single last block
    // after the whole pipeline is finished, separated by __syncthreads()).
    double*   dred = (double*)s_dyn;               // 128 * 8B
    unsigned* hist = (unsigned*)(dred + 128);      // 256 * 4B

    const int tid  = threadIdx.x;
    const int lane = tid & 31;
    const int wid  = tid >> 5;

    float* stage[2] = { s_dyn + wid * 2 * SLICE_F,
                        s_dyn + wid * 2 * SLICE_F + SLICE_F };
    const uint32_t st_a0 = (uint32_t)__cvta_generic_to_shared(stage[0]);
    const uint32_t st_a1 = (uint32_t)__cvta_generic_to_shared(stage[1]);
    const uint32_t st_addr[2] = { st_a0, st_a1 };

    // ---- per-warp label-dtype detection: 32 int2 (256 B, L2-hot).
    // int64 labels in [0,81) -> odd words all zero; 32 random int32 labels
    // all-zero has p = (1/81)^32 ~ 1e-61.
    const int  badw = ((const int2*)ct)[lane].y;
    const bool is64 = !__any_sync(FULLMASK, badw);

    const int s_base = (blockIdx.x * NWARP + wid) * K_SL;

    // prefetch slices 0,1
    issue_slice(conf, st_addr[0], s_base, lane);
    cp_commit();
    issue_slice(conf, st_addr[1], s_base + 1, lane);
    cp_commit();

    float a_all = 0.f, a_pos = 0.f, a_loc = 0.f;
    int   a_cnt = 0, cur_b = -1;

    #pragma unroll
    for (int i = 0; i < K_SL; i++) {
        const int s  = s_base + i;
        const int b  = s / SL_PER_B;
        const int j  = s % SL_PER_B;
        const int p0 = j * WROWS;
        const int nr = min(WROWS, PRIORS - p0);
        const long long gw = (long long)b * PRIORS + p0;

        if (b != cur_b) {                          // warp-scope batch flush
            if (cur_b >= 0) {
                float aa = a_all, pp = a_pos, ll = a_loc; int nc = a_cnt;
                #pragma unroll
                for (int o = 16; o > 0; o >>= 1) {
                    aa += __shfl_down_sync(FULLMASK, aa, o);
                    pp += __shfl_down_sync(FULLMASK, pp, o);
                    ll += __shfl_down_sync(FULLMASK, ll, o);
                    nc += __shfl_down_sync(FULLMASK, nc, o);
                }
                if (lane == 0) {
                    atomicAdd(&g_sum_all[cur_b], (double)aa);
                    atomicAdd(&g_sum_pos[cur_b], (double)pp);
                    atomicAdd(&g_sum_loc[cur_b], (double)ll);
                    atomicAdd(&g_num_pos[cur_b], nc);
                }
                a_all = a_pos = a_loc = 0.f; a_cnt = 0;
            }
            cur_b = b;
        }

        cp_wait1();            // my copies for slice i done (<=1 group pending)
        __syncwarp();          // whole warp's copies visible

        const float* st = stage[i & 1];
        if (lane < nr) {
            // label + loc loads up front; latency hides under the exps
            const int t = is64 ? (int)((const long long*)ct)[gw + lane]
                               : ((const int*)ct)[gw + lane];
            const float4 d4 = loc[gw + lane];
            const float4 t4 = loct[gw + lane];

            // Row L starts at float 81*L. Read the aligned 82-float window
            // starting at float2 floor(81*L/2); subtract the one stray exp
            // (even L: trailing .y; odd L: leading .x). Windows stay inside
            // the staged nr*81 floats for nr in {32, 28}.
            const float2* f2p = (const float2*)st + ((81 * lane) >> 1);
            float e0 = 0.f, e1 = 0.f, e2 = 0.f, e3 = 0.f;
            #pragma unroll
            for (int q = 0; q < 40; q += 4) {
                const float2 f0 = f2p[q];
                const float2 f1 = f2p[q + 1];
                const float2 f2 = f2p[q + 2];
                const float2 f3 = f2p[q + 3];
                e0 += __expf(f0.x) + __expf(f0.y);
                e1 += __expf(f1.x) + __expf(f1.y);
                e2 += __expf(f2.x) + __expf(f2.y);
                e3 += __expf(f3.x) + __expf(f3.y);
            }
            const float2 fl = f2p[40];
            float sum = (((e0 + e1) + (e2 + e3)) + __expf(fl.x)) + __expf(fl.y);
            const float stray = (lane & 1) ? f2p[0].x : fl.y;
            sum -= __expf(stray);

            const float tv  = st[81 * lane + t];
            const float nll = __logf(sum) - tv;
            const bool  pos = (t > 0);

            g_vrank[gw + lane] = pos ? 0.f : nll;
            a_all += nll;
            if (pos) {
                a_pos += nll; a_cnt++;
                float dx = d4.x - t4.x, dy = d4.y - t4.y;
                float dz = d4.z - t4.z, dw = d4.w - t4.w;
                float ax = fabsf(dx), ay = fabsf(dy);
                float az = fabsf(dz), aw = fabsf(dw);
                a_loc += ((ax < 1.f) ? 0.5f * dx * dx : ax - 0.5f)
                       + ((ay < 1.f) ? 0.5f * dy * dy : ay - 0.5f)
                       + ((az < 1.f) ? 0.5f * dz * dz : az - 0.5f)
                       + ((aw < 1.f) ? 0.5f * dw * dw : aw - 0.5f);
            }
        }
        __syncwarp();          // warpmates done reading this stage
        if (i + 2 < K_SL)
            issue_slice(conf, st_addr[i & 1], s_base + i + 2, lane);
        cp_commit();           // (possibly empty) keeps group counts aligned
    }

    // final warp flush
    {
        float aa = a_all, pp = a_pos, ll = a_loc; int nc = a_cnt;
        #pragma unroll
        for (int o = 16; o > 0; o >>= 1) {
            aa += __shfl_down_sync(FULLMASK, aa, o);
            pp += __shfl_down_sync(FULLMASK, pp, o);
            ll += __shfl_down_sync(FULLMASK, ll, o);
            nc += __shfl_down_sync(FULLMASK, nc, o);
        }
        if (lane == 0) {
            atomicAdd(&g_sum_all[cur_b], (double)aa);
            atomicAdd(&g_sum_pos[cur_b], (double)pp);
            atomicAdd(&g_sum_loc[cur_b], (double)ll);
            atomicAdd(&g_num_pos[cur_b], nc);
        }
    }

    __syncthreads();
    if (tid == 0) {
        __threadfence();
        s_last = atomicAdd(&g_done, 1u);
    }
    __syncthreads();
    if (s_last != (unsigned)(gridDim.x - 1)) return;

    // ======================= fused finalizer (last block) ===================
    __threadfence();
    if (tid < 32) {
        const int    npb  = ((volatile int*)g_num_pos)[tid];
        const double sall = ((volatile double*)g_sum_all)[tid];
        const double sloc = ((volatile double*)g_sum_loc)[tid];
        const long long nn = min((long long)3 * npb, (long long)(PRIORS - 1));
        const bool rare = (nn < (long long)(PRIORS - npb));
        const unsigned rm = __ballot_sync(FULLMASK, rare);
        double c = rare ? 0.0 : sall;
        double l = sloc;
        int    n = npb;
        #pragma unroll
        for (int o = 16; o > 0; o >>= 1) {
            c += __shfl_down_sync(FULLMASK, c, o);
            l += __shfl_down_sync(FULLMASK, l, o);
            n += __shfl_down_sync(FULLMASK, n, o);
        }
        if (tid == 0) { sh_lc = c; sh_ll = l; sh_n = n; sh_rare = rm; }
    }
    __syncthreads();

    double loss_c = sh_lc;
    unsigned rmask = sh_rare;
    // rare path: exact top-k radix select per flagged batch (expected none)
    while (rmask) {
        const int rb = __ffs(rmask) - 1;
        rmask &= rmask - 1;
        const int npb = ((volatile int*)g_num_pos)[rb];
        int kk = (int)min((long long)3 * npb, (long long)(PRIORS - 1));
        const float* v = g_vrank + (long long)rb * PRIORS;
        unsigned prefix = 0;
        for (int shift = 24; shift >= 0; shift -= 8) {
            for (int i = tid; i < 256; i += TPB) hist[i] = 0;
            __syncthreads();
            const unsigned mask_hi =
                (shift == 24) ? 0u : (0xFFFFFFFFu << (shift + 8));
            for (int i = tid; i < PRIORS; i += TPB) {
                const unsigned bits = __float_as_uint(v[i]);
                if ((bits & mask_hi) == prefix)
                    atomicAdd(&hist[(bits >> shift) & 255], 1u);
            }
            __syncthreads();
            if (tid == 0) {
                int acc = 0, bin = 255;
                for (; bin > 0; --bin) {
                    if (acc + (int)hist[bin] >= kk) break;
                    acc += (int)hist[bin];
                }
                sh_prefix = prefix | ((unsigned)bin << shift);
                sh_k      = kk - acc;
            }
            __syncthreads();
            prefix = sh_prefix; kk = sh_k;
            __syncthreads();
        }
        double local = 0.0;
        for (int i = tid; i < PRIORS; i += TPB) {
            const unsigned bits = __float_as_uint(v[i]);
            if (bits > prefix) local += (double)v[i];
        }
        dred[tid] = local;
        if (tid < 128 - TPB) dred[TPB + tid] = 0.0;   // pad to 128 slots
        __syncthreads();
        for (int st = 64; st > 0; st >>= 1) {
            if (tid < st) dred[tid] += dred[tid + st];
            __syncthreads();
        }
        if (tid == 0) {
            loss_c += ((volatile double*)g_sum_pos)[rb] + dred[0] +
                      (double)kk * (double)__uint_as_float(prefix);
        }
        __syncthreads();
    }

    if (tid == 0) {
        const double N = (double)sh_n;
        if (out_size >= 1) out[0] = (float)(loss_c / N);
        if (out_size >= 2) out[1] = (float)(sh_ll / N);
    }

    // reset globals for the next graph replay
    if (tid < BATCH) {
        g_sum_all[tid] = 0.0; g_sum_pos[tid] = 0.0;
        g_sum_loc[tid] = 0.0; g_num_pos[tid] = 0;
    }
    if (tid == 0) g_done = 0;
}

extern "C" void kernel_launch(void* const* d_in, const int* in_sizes, int n_in,
                              void* d_out, int out_size) {
    const float*  conf = (const float*)d_in[0];
    const float4* loc  = (const float4*)d_in[1];
    const void*   ct   = d_in[2];
    const float4* loct = (const float4*)d_in[3];
    float*        out  = (float*)d_out;
    (void)in_sizes; (void)n_in;

    cudaFuncSetAttribute(k_main, cudaFuncAttributeMaxDynamicSharedMemorySize,
                         SMEM_BYTES);
    k_main<<<GRID_MAIN, TPB, SMEM_BYTES>>>(conf, loc, ct, loct, out, out_size);
}